// round 1
// baseline (speedup 1.0000x reference)
#include <cuda_runtime.h>
#include <math.h>

#define BATCH 4
#define BLOCK_NUM 16
#define BL 512
#define DIM 512
#define NROWS (BATCH*BLOCK_NUM*BL)   /* 32768 */
#define NBLK  (BATCH*BLOCK_NUM)      /* 64    */

// Scratch (allocation-free rule: __device__ globals)
__device__ float g_Q[(size_t)NROWS*DIM];
__device__ float g_K[(size_t)NROWS*DIM];
__device__ float g_V[(size_t)NROWS*DIM];
__device__ float g_S[(size_t)NBLK*BL*BL];

// ---------------------------------------------------------------------------
// SGEMM NN: C[M,N] = A[M,K] @ B[K,N] + bias   (M=NROWS, N=K=DIM)
// 128x128 tile, BK=8, 256 threads, 8x8 per thread.
// ---------------------------------------------------------------------------
__global__ __launch_bounds__(256, 2)
void sgemm_qkv(const float* __restrict__ A, const float* __restrict__ B,
               const float* __restrict__ bias, float* __restrict__ C) {
    __shared__ float As[8][128];
    __shared__ float Bs[8][128];
    const int tid  = threadIdx.x;
    const int bm   = blockIdx.y * 128;
    const int bn   = blockIdx.x * 128;
    const int arow = tid >> 1, acol = (tid & 1) << 2;
    const int brow = tid >> 5, bcol = (tid & 31) << 2;
    const int tx   = tid & 15, ty   = tid >> 4;

    float acc[8][8];
#pragma unroll
    for (int i = 0; i < 8; i++)
#pragma unroll
        for (int j = 0; j < 8; j++) acc[i][j] = 0.f;

    const float* Ap = A + (size_t)(bm + arow) * DIM + acol;
    const float* Bp = B + (size_t)brow * DIM + bn + bcol;

    for (int k0 = 0; k0 < DIM; k0 += 8) {
        float4 av = *(const float4*)(Ap + k0);
        float4 bv = *(const float4*)(Bp + (size_t)k0 * DIM);
        As[acol+0][arow] = av.x; As[acol+1][arow] = av.y;
        As[acol+2][arow] = av.z; As[acol+3][arow] = av.w;
        *(float4*)&Bs[brow][bcol] = bv;
        __syncthreads();
#pragma unroll
        for (int k = 0; k < 8; k++) {
            float4 a0 = *(const float4*)&As[k][ty*8];
            float4 a1 = *(const float4*)&As[k][ty*8+4];
            float4 b0 = *(const float4*)&Bs[k][tx*8];
            float4 b1 = *(const float4*)&Bs[k][tx*8+4];
            float ar[8] = {a0.x,a0.y,a0.z,a0.w,a1.x,a1.y,a1.z,a1.w};
            float br[8] = {b0.x,b0.y,b0.z,b0.w,b1.x,b1.y,b1.z,b1.w};
#pragma unroll
            for (int i = 0; i < 8; i++)
#pragma unroll
                for (int j = 0; j < 8; j++)
                    acc[i][j] = fmaf(ar[i], br[j], acc[i][j]);
        }
        __syncthreads();
    }
#pragma unroll
    for (int i = 0; i < 8; i++) {
        int row = bm + ty*8 + i;
        float* Cp = C + (size_t)row * DIM + bn + tx*8;
#pragma unroll
        for (int j = 0; j < 8; j += 4) {
            const float* bp = bias + bn + tx*8 + j;
            float4 v;
            v.x = acc[i][j+0] + bp[0];
            v.y = acc[i][j+1] + bp[1];
            v.z = acc[i][j+2] + bp[2];
            v.w = acc[i][j+3] + bp[3];
            *(float4*)(Cp + j) = v;
        }
    }
}

// ---------------------------------------------------------------------------
// Scores (NT): S[q,k] = scale * sum_d Q[q,d]*K[k,d] + (1-mask)*(-1e10)
// One (b,n) block per blockIdx.z; 128x128 tiles over 512x512.
// ---------------------------------------------------------------------------
__global__ __launch_bounds__(256, 2)
void sgemm_scores(const float* __restrict__ mask) {
    const int z  = blockIdx.z;
    const float* A = g_Q + (size_t)z * BL * DIM;
    const float* B = g_K + (size_t)z * BL * DIM;
    float*       C = g_S + (size_t)z * BL * BL;

    __shared__ float As[8][128];
    __shared__ float Bs[8][128];
    const int tid  = threadIdx.x;
    const int bm   = blockIdx.y * 128;
    const int bn   = blockIdx.x * 128;
    const int lrow = tid >> 1, lcol = (tid & 1) << 2;
    const int tx   = tid & 15, ty   = tid >> 4;

    float acc[8][8];
#pragma unroll
    for (int i = 0; i < 8; i++)
#pragma unroll
        for (int j = 0; j < 8; j++) acc[i][j] = 0.f;

    const float* Ap = A + (size_t)(bm + lrow) * DIM + lcol;
    const float* Bp = B + (size_t)(bn + lrow) * DIM + lcol;

    for (int k0 = 0; k0 < DIM; k0 += 8) {
        float4 av = *(const float4*)(Ap + k0);
        float4 bv = *(const float4*)(Bp + k0);
        As[lcol+0][lrow] = av.x; As[lcol+1][lrow] = av.y;
        As[lcol+2][lrow] = av.z; As[lcol+3][lrow] = av.w;
        Bs[lcol+0][lrow] = bv.x; Bs[lcol+1][lrow] = bv.y;
        Bs[lcol+2][lrow] = bv.z; Bs[lcol+3][lrow] = bv.w;
        __syncthreads();
#pragma unroll
        for (int k = 0; k < 8; k++) {
            float4 a0 = *(const float4*)&As[k][ty*8];
            float4 a1 = *(const float4*)&As[k][ty*8+4];
            float4 b0 = *(const float4*)&Bs[k][tx*8];
            float4 b1 = *(const float4*)&Bs[k][tx*8+4];
            float ar[8] = {a0.x,a0.y,a0.z,a0.w,a1.x,a1.y,a1.z,a1.w};
            float br[8] = {b0.x,b0.y,b0.z,b0.w,b1.x,b1.y,b1.z,b1.w};
#pragma unroll
            for (int i = 0; i < 8; i++)
#pragma unroll
                for (int j = 0; j < 8; j++)
                    acc[i][j] = fmaf(ar[i], br[j], acc[i][j]);
        }
        __syncthreads();
    }
    const float scale = 0.04419417382415922f;  // 1/sqrt(512)
#pragma unroll
    for (int i = 0; i < 8; i++) {
        int q = bm + ty*8 + i;
        size_t grow = (size_t)z * BL + q;          // global row: aligns with mask layout
        float*       Cp = C + (size_t)q * BL + bn + tx*8;
        const float* Mp = mask + grow * DIM + bn + tx*8;
#pragma unroll
        for (int j = 0; j < 8; j += 4) {
            float4 mv = *(const float4*)(Mp + j);
            float4 v;
            v.x = acc[i][j+0]*scale + (1.f - mv.x) * (-1e10f);
            v.y = acc[i][j+1]*scale + (1.f - mv.y) * (-1e10f);
            v.z = acc[i][j+2]*scale + (1.f - mv.z) * (-1e10f);
            v.w = acc[i][j+3]*scale + (1.f - mv.w) * (-1e10f);
            *(float4*)(Cp + j) = v;
        }
    }
}

// ---------------------------------------------------------------------------
// Row softmax over 512 elements; one CTA (128 threads) per row, in-place on g_S
// ---------------------------------------------------------------------------
__global__ __launch_bounds__(128)
void softmax_rows() {
    const size_t row = blockIdx.x;
    float4* p = (float4*)(g_S + row * BL);
    const int tid = threadIdx.x;
    float4 v = p[tid];

    float m = fmaxf(fmaxf(v.x, v.y), fmaxf(v.z, v.w));
#pragma unroll
    for (int o = 16; o; o >>= 1) m = fmaxf(m, __shfl_xor_sync(0xFFFFFFFFu, m, o));
    __shared__ float sm[4];
    if ((tid & 31) == 0) sm[tid >> 5] = m;
    __syncthreads();
    m = fmaxf(fmaxf(sm[0], sm[1]), fmaxf(sm[2], sm[3]));

    v.x = __expf(v.x - m); v.y = __expf(v.y - m);
    v.z = __expf(v.z - m); v.w = __expf(v.w - m);
    float s = v.x + v.y + v.z + v.w;
#pragma unroll
    for (int o = 16; o; o >>= 1) s += __shfl_xor_sync(0xFFFFFFFFu, s, o);
    __shared__ float ss[4];
    if ((tid & 31) == 0) ss[tid >> 5] = s;
    __syncthreads();
    s = ss[0] + ss[1] + ss[2] + ss[3];

    float r = 1.f / s;
    v.x *= r; v.y *= r; v.z *= r; v.w *= r;
    p[tid] = v;
}

// ---------------------------------------------------------------------------
// Output (NN): O[q,d] = sum_k P[q,k]*V[k,d] + X[q,d]  (residual fused)
// ---------------------------------------------------------------------------
__global__ __launch_bounds__(256, 2)
void sgemm_out(const float* __restrict__ X, float* __restrict__ Out) {
    const int z = blockIdx.z;
    const float* A = g_S + (size_t)z * BL * BL;   // P
    const float* B = g_V + (size_t)z * BL * DIM;  // V
    float*       C = Out + (size_t)z * BL * DIM;
    const float* R = X   + (size_t)z * BL * DIM;

    __shared__ float As[8][128];
    __shared__ float Bs[8][128];
    const int tid  = threadIdx.x;
    const int bm   = blockIdx.y * 128;
    const int bn   = blockIdx.x * 128;
    const int arow = tid >> 1, acol = (tid & 1) << 2;
    const int brow = tid >> 5, bcol = (tid & 31) << 2;
    const int tx   = tid & 15, ty   = tid >> 4;

    float acc[8][8];
#pragma unroll
    for (int i = 0; i < 8; i++)
#pragma unroll
        for (int j = 0; j < 8; j++) acc[i][j] = 0.f;

    const float* Ap = A + (size_t)(bm + arow) * BL + acol;
    const float* Bp = B + (size_t)brow * DIM + bn + bcol;

    for (int k0 = 0; k0 < BL; k0 += 8) {
        float4 av = *(const float4*)(Ap + k0);
        float4 bv = *(const float4*)(Bp + (size_t)k0 * DIM);
        As[acol+0][arow] = av.x; As[acol+1][arow] = av.y;
        As[acol+2][arow] = av.z; As[acol+3][arow] = av.w;
        *(float4*)&Bs[brow][bcol] = bv;
        __syncthreads();
#pragma unroll
        for (int k = 0; k < 8; k++) {
            float4 a0 = *(const float4*)&As[k][ty*8];
            float4 a1 = *(const float4*)&As[k][ty*8+4];
            float4 b0 = *(const float4*)&Bs[k][tx*8];
            float4 b1 = *(const float4*)&Bs[k][tx*8+4];
            float ar[8] = {a0.x,a0.y,a0.z,a0.w,a1.x,a1.y,a1.z,a1.w};
            float br[8] = {b0.x,b0.y,b0.z,b0.w,b1.x,b1.y,b1.z,b1.w};
#pragma unroll
            for (int i = 0; i < 8; i++)
#pragma unroll
                for (int j = 0; j < 8; j++)
                    acc[i][j] = fmaf(ar[i], br[j], acc[i][j]);
        }
        __syncthreads();
    }
#pragma unroll
    for (int i = 0; i < 8; i++) {
        int q = bm + ty*8 + i;
        float*       Cp = C + (size_t)q * DIM + bn + tx*8;
        const float* Rp = R + (size_t)q * DIM + bn + tx*8;
#pragma unroll
        for (int j = 0; j < 8; j += 4) {
            float4 rv = *(const float4*)(Rp + j);
            float4 v;
            v.x = acc[i][j+0] + rv.x;
            v.y = acc[i][j+1] + rv.y;
            v.z = acc[i][j+2] + rv.z;
            v.w = acc[i][j+3] + rv.w;
            *(float4*)(Cp + j) = v;
        }
    }
}

// ---------------------------------------------------------------------------
// LayerNorm rows in-place on d_out: 512 elems/row, eps=1e-3, gamma=1, beta=0
// ---------------------------------------------------------------------------
__global__ __launch_bounds__(128)
void ln_rows(float* __restrict__ out) {
    const size_t row = blockIdx.x;
    float4* p = (float4*)(out + row * DIM);
    const int tid = threadIdx.x;
    float4 v = p[tid];

    float s  = v.x + v.y + v.z + v.w;
    float sq = v.x*v.x + v.y*v.y + v.z*v.z + v.w*v.w;
#pragma unroll
    for (int o = 16; o; o >>= 1) {
        s  += __shfl_xor_sync(0xFFFFFFFFu, s,  o);
        sq += __shfl_xor_sync(0xFFFFFFFFu, sq, o);
    }
    __shared__ float ws[4], wq[4];
    if ((tid & 31) == 0) { ws[tid >> 5] = s; wq[tid >> 5] = sq; }
    __syncthreads();
    s  = ws[0] + ws[1] + ws[2] + ws[3];
    sq = wq[0] + wq[1] + wq[2] + wq[3];

    const float inv = 1.f / (float)DIM;
    float mean = s * inv;
    float var  = sq * inv - mean * mean;
    float r = rsqrtf(var + 1e-3f);
    v.x = (v.x - mean) * r; v.y = (v.y - mean) * r;
    v.z = (v.z - mean) * r; v.w = (v.w - mean) * r;
    p[tid] = v;
}

// ---------------------------------------------------------------------------
extern "C" void kernel_launch(void* const* d_in, const int* in_sizes, int n_in,
                              void* d_out, int out_size) {
    const float* X    = (const float*)d_in[0];
    const float* mask = (const float*)d_in[1];
    const float* dw1  = (const float*)d_in[2];
    const float* dw2  = (const float*)d_in[3];
    const float* dw3  = (const float*)d_in[4];
    const float* db1  = (const float*)d_in[5];
    const float* db2  = (const float*)d_in[6];
    const float* db3  = (const float*)d_in[7];
    float* out = (float*)d_out;

    float *Q, *K, *V;
    cudaGetSymbolAddress((void**)&Q, g_Q);
    cudaGetSymbolAddress((void**)&K, g_K);
    cudaGetSymbolAddress((void**)&V, g_V);

    dim3 gQKV(DIM/128, NROWS/128);          // (4, 256)
    sgemm_qkv<<<gQKV, 256>>>(X, dw1, db1, Q);
    sgemm_qkv<<<gQKV, 256>>>(X, dw2, db2, K);
    sgemm_qkv<<<gQKV, 256>>>(X, dw3, db3, V);

    dim3 gS(BL/128, BL/128, NBLK);          // (4, 4, 64)
    sgemm_scores<<<gS, 256>>>(mask);

    softmax_rows<<<NBLK*BL, 128>>>();

    dim3 gO(DIM/128, BL/128, NBLK);         // (4, 4, 64)
    sgemm_out<<<gO, 256>>>(X, out);

    ln_rows<<<NROWS, 128>>>(out);
}

// round 3
// speedup vs baseline: 3.5538x; 3.5538x over previous
#include <cuda_runtime.h>
#include <cstdint>
#include <math.h>

#define BL 512
#define DIM 512
#define NROWS 32768
#define NBLK 64

// Scratch (allocation-free rule: __device__ globals)
__device__ float g_Q [(size_t)NROWS*DIM];
__device__ float g_K [(size_t)NROWS*DIM];
__device__ float g_V [(size_t)NROWS*DIM];
__device__ float g_S [(size_t)NBLK*BL*BL];
__device__ float g_Xr[(size_t)NROWS*DIM];
__device__ float g_Wr[(size_t)3*DIM*DIM];

// ---------------------------------------------------------------------------
__device__ __forceinline__ uint32_t smem_u32(const void* p) {
    uint32_t a;
    asm("{ .reg .u64 t; cvta.to.shared.u64 t, %1; cvt.u32.u64 %0, t; }" : "=r"(a) : "l"(p));
    return a;
}
__device__ __forceinline__ float rna(float x) {
    uint32_t u; asm("cvt.rna.tf32.f32 %0, %1;" : "=r"(u) : "f"(x));
    return __uint_as_float(u);
}
#define CP16(dst, src) \
    asm volatile("cp.async.cg.shared.global [%0], [%1], 16;" :: "r"(dst), "l"(src))
#define CPCOMMIT() asm volatile("cp.async.commit_group;" ::: "memory")
#define CPWAIT1()  asm volatile("cp.async.wait_group 1;" ::: "memory")
#define CPWAIT0()  asm volatile("cp.async.wait_group 0;" ::: "memory")

__device__ __forceinline__ void mma8(float* c, const float* a, const float* b) {
    asm volatile(
        "mma.sync.aligned.m16n8k8.row.col.f32.tf32.tf32.f32 "
        "{%0,%1,%2,%3},{%4,%5,%6,%7},{%8,%9},{%0,%1,%2,%3};"
        : "+f"(c[0]), "+f"(c[1]), "+f"(c[2]), "+f"(c[3])
        : "r"(__float_as_uint(a[0])), "r"(__float_as_uint(a[1])),
          "r"(__float_as_uint(a[2])), "r"(__float_as_uint(a[3])),
          "r"(__float_as_uint(b[0])), "r"(__float_as_uint(b[1])));
}

// ---------------------------------------------------------------------------
// tf32 mma.sync GEMM, CTA tile 128x128, 8 warps (warp tile 32x64), BK=32,
// double-buffered cp.async.
// MODE 0: C = A @ B      + bias (row vec)   A:[M,512] B:[512,N](W) aux=bias
// MODE 1: C = scale*(A @ B^T) + mask-bias   A=Q B=K (both [512,512] K-major)
// MODE 2: C = A @ B      + residual         A=P B=V aux=X
// ---------------------------------------------------------------------------
#define AS_STRIDE 36
#define BS_NN_STRIDE 136
#define STAGE_FLOATS 4608            /* 18432 B, covers both B layouts */
#define SMEM_BYTES (4*STAGE_FLOATS*4)

template<int MODE>
__global__ void __launch_bounds__(256, 2)
tc_gemm(const float* __restrict__ Ag, const float* __restrict__ Bg,
        const float* __restrict__ aux, float* __restrict__ Cg) {
    extern __shared__ float sm[];
    const uint32_t sb = smem_u32(sm);
    const int tid  = threadIdx.x;
    const int lane = tid & 31, wid = tid >> 5;
    const int wm = wid & 3, wn = wid >> 1 & 0 ? 0 : (wid >> 2); // wn = wid>>2
    const int q  = lane & 3, rg = lane >> 2;

    const size_t zoff = (size_t)blockIdx.z * (BL * DIM);
    const int bm = blockIdx.y * 128, bn = blockIdx.x * 128;
    const float* A = Ag + (MODE == 0 ? (size_t)0 : zoff) + (size_t)bm * DIM;
    const float* B;
    if (MODE == 1)      B = Bg + zoff + (size_t)bn * DIM;  // K rows (NT)
    else if (MODE == 2) B = Bg + zoff + bn;                // V, NN
    else                B = Bg + bn;                       // W, NN

    float acc[2][8][4];
#pragma unroll
    for (int i = 0; i < 2; i++)
#pragma unroll
        for (int j = 0; j < 8; j++)
#pragma unroll
            for (int k = 0; k < 4; k++) acc[i][j][k] = 0.f;

    // ---- async load of K-chunk c into stage s ----
    auto load = [&](int c, int s) {
        const uint32_t as = sb + (uint32_t)s * STAGE_FLOATS * 4;
        const uint32_t bs = sb + (uint32_t)(2 + s) * STAGE_FLOATS * 4;
#pragma unroll
        for (int t = 0; t < 4; t++) {
            int idx = tid + t * 256;
            int r = idx >> 3, c4 = idx & 7;
            CP16(as + (uint32_t)(r * AS_STRIDE + c4 * 4) * 4,
                 A + (size_t)r * DIM + c * 32 + c4 * 4);
            if (MODE == 1) {
                CP16(bs + (uint32_t)(r * AS_STRIDE + c4 * 4) * 4,
                     B + (size_t)r * DIM + c * 32 + c4 * 4);
            } else {
                int kr = idx >> 5, n4 = idx & 31;
                CP16(bs + (uint32_t)(kr * BS_NN_STRIDE + n4 * 4) * 4,
                     B + (size_t)(c * 32 + kr) * DIM + n4 * 4);
            }
        }
        CPCOMMIT();
    };

    auto compute = [&](int s) {
        const float* as = sm + (size_t)s * STAGE_FLOATS;
        const float* bs = sm + (size_t)(2 + s) * STAGE_FLOATS;
#pragma unroll
        for (int ks = 0; ks < 4; ks++) {
            const int kk = ks * 8;
            float af[2][4];
#pragma unroll
            for (int mt = 0; mt < 2; mt++) {
                const int r0 = wm * 32 + mt * 16 + rg;
                af[mt][0] = as[r0 * AS_STRIDE + kk + q];
                af[mt][1] = as[(r0 + 8) * AS_STRIDE + kk + q];
                af[mt][2] = as[r0 * AS_STRIDE + kk + q + 4];
                af[mt][3] = as[(r0 + 8) * AS_STRIDE + kk + q + 4];
            }
            float bf[8][2];
#pragma unroll
            for (int nt = 0; nt < 8; nt++) {
                const int n0 = wn * 64 + nt * 8 + rg;
                if (MODE == 1) {
                    bf[nt][0] = bs[n0 * AS_STRIDE + kk + q];
                    bf[nt][1] = bs[n0 * AS_STRIDE + kk + q + 4];
                } else {
                    bf[nt][0] = bs[(kk + q) * BS_NN_STRIDE + n0];
                    bf[nt][1] = bs[(kk + q + 4) * BS_NN_STRIDE + n0];
                }
            }
#pragma unroll
            for (int mt = 0; mt < 2; mt++)
#pragma unroll
                for (int nt = 0; nt < 8; nt++)
                    mma8(acc[mt][nt], af[mt], bf[nt]);
        }
    };

    load(0, 0);
    for (int c = 0; c < 16; c++) {
        const int s = c & 1;
        if (c + 1 < 16) { load(c + 1, s ^ 1); CPWAIT1(); }
        else           { CPWAIT0(); }
        __syncthreads();
        compute(s);
        __syncthreads();
    }

    // ---- epilogue ----
    const float scale = 0.04419417382415922f;  // 1/sqrt(512)
#pragma unroll
    for (int mt = 0; mt < 2; mt++)
#pragma unroll
    for (int nt = 0; nt < 8; nt++) {
        const int rl0 = bm + wm * 32 + mt * 16 + rg;
        const int cl  = bn + wn * 64 + nt * 8 + 2 * q;
#pragma unroll
        for (int h = 0; h < 2; h++) {
            const int r = rl0 + h * 8;
            float v0 = acc[mt][nt][2 * h + 0];
            float v1 = acc[mt][nt][2 * h + 1];
            size_t base;
            if (MODE == 0) {
                base = (size_t)r * DIM + cl;
                float2 bv = *(const float2*)(aux + cl);
                v0 = rna(v0 + bv.x);
                v1 = rna(v1 + bv.y);
            } else if (MODE == 1) {
                const size_t grow = (size_t)blockIdx.z * BL + r;
                base = grow * DIM + cl;          // mask & S share flat layout
                float2 mv = *(const float2*)(aux + base);
                v0 = v0 * scale + (1.f - mv.x) * (-1e10f);
                v1 = v1 * scale + (1.f - mv.y) * (-1e10f);
            } else {
                const size_t grow = (size_t)blockIdx.z * BL + r;
                base = grow * DIM + cl;
                float2 rv = *(const float2*)(aux + base);
                v0 += rv.x;
                v1 += rv.y;
            }
            *(float2*)(Cg + base) = make_float2(v0, v1);
        }
    }
}

// ---------------------------------------------------------------------------
// Elementwise RNA-round copy (prepare exact-tf32 MMA operands)
// ---------------------------------------------------------------------------
__global__ __launch_bounds__(256)
void rna_copy(const float* __restrict__ src, float* __restrict__ dst, int n4) {
    int i = blockIdx.x * 256 + threadIdx.x;
    if (i < n4) {
        float4 v = ((const float4*)src)[i];
        v.x = rna(v.x); v.y = rna(v.y); v.z = rna(v.z); v.w = rna(v.w);
        ((float4*)dst)[i] = v;
    }
}

// ---------------------------------------------------------------------------
// Row softmax over 512 elems (in-place on g_S), output RNA-rounded for mma
// ---------------------------------------------------------------------------
__global__ __launch_bounds__(128)
void softmax_rows() {
    const size_t row = blockIdx.x;
    float4* p = (float4*)(g_S + row * BL);
    const int tid = threadIdx.x;
    float4 v = p[tid];
    float m = fmaxf(fmaxf(v.x, v.y), fmaxf(v.z, v.w));
#pragma unroll
    for (int o = 16; o; o >>= 1) m = fmaxf(m, __shfl_xor_sync(0xFFFFFFFFu, m, o));
    __shared__ float sm[4];
    if ((tid & 31) == 0) sm[tid >> 5] = m;
    __syncthreads();
    m = fmaxf(fmaxf(sm[0], sm[1]), fmaxf(sm[2], sm[3]));
    v.x = __expf(v.x - m); v.y = __expf(v.y - m);
    v.z = __expf(v.z - m); v.w = __expf(v.w - m);
    float s = v.x + v.y + v.z + v.w;
#pragma unroll
    for (int o = 16; o; o >>= 1) s += __shfl_xor_sync(0xFFFFFFFFu, s, o);
    __shared__ float ss[4];
    if ((tid & 31) == 0) ss[tid >> 5] = s;
    __syncthreads();
    s = ss[0] + ss[1] + ss[2] + ss[3];
    float r = 1.f / s;
    v.x = rna(v.x * r); v.y = rna(v.y * r);
    v.z = rna(v.z * r); v.w = rna(v.w * r);
    p[tid] = v;
}

// ---------------------------------------------------------------------------
// LayerNorm rows in-place on d_out (eps=1e-3)
// ---------------------------------------------------------------------------
__global__ __launch_bounds__(128)
void ln_rows(float* __restrict__ out) {
    const size_t row = blockIdx.x;
    float4* p = (float4*)(out + row * DIM);
    const int tid = threadIdx.x;
    float4 v = p[tid];
    float s  = v.x + v.y + v.z + v.w;
    float sq = v.x*v.x + v.y*v.y + v.z*v.z + v.w*v.w;
#pragma unroll
    for (int o = 16; o; o >>= 1) {
        s  += __shfl_xor_sync(0xFFFFFFFFu, s,  o);
        sq += __shfl_xor_sync(0xFFFFFFFFu, sq, o);
    }
    __shared__ float ws[4], wq[4];
    if ((tid & 31) == 0) { ws[tid >> 5] = s; wq[tid >> 5] = sq; }
    __syncthreads();
    s  = ws[0] + ws[1] + ws[2] + ws[3];
    sq = wq[0] + wq[1] + wq[2] + wq[3];
    const float inv = 1.f / (float)DIM;
    float mean = s * inv;
    float var  = sq * inv - mean * mean;
    float r = rsqrtf(var + 1e-3f);
    v.x = (v.x - mean) * r; v.y = (v.y - mean) * r;
    v.z = (v.z - mean) * r; v.w = (v.w - mean) * r;
    p[tid] = v;
}

// ---------------------------------------------------------------------------
extern "C" void kernel_launch(void* const* d_in, const int* in_sizes, int n_in,
                              void* d_out, int out_size) {
    const float* X    = (const float*)d_in[0];
    const float* mask = (const float*)d_in[1];
    const float* dw1  = (const float*)d_in[2];
    const float* dw2  = (const float*)d_in[3];
    const float* dw3  = (const float*)d_in[4];
    const float* db1  = (const float*)d_in[5];
    const float* db2  = (const float*)d_in[6];
    const float* db3  = (const float*)d_in[7];
    float* out = (float*)d_out;

    float *Q, *K, *V, *S, *Xr, *Wr;
    cudaGetSymbolAddress((void**)&Q,  g_Q);
    cudaGetSymbolAddress((void**)&K,  g_K);
    cudaGetSymbolAddress((void**)&V,  g_V);
    cudaGetSymbolAddress((void**)&S,  g_S);
    cudaGetSymbolAddress((void**)&Xr, g_Xr);
    cudaGetSymbolAddress((void**)&Wr, g_Wr);

    static int attr_done = 0;
    if (!attr_done) {
        cudaFuncSetAttribute(tc_gemm<0>, cudaFuncAttributeMaxDynamicSharedMemorySize, SMEM_BYTES);
        cudaFuncSetAttribute(tc_gemm<1>, cudaFuncAttributeMaxDynamicSharedMemorySize, SMEM_BYTES);
        cudaFuncSetAttribute(tc_gemm<2>, cudaFuncAttributeMaxDynamicSharedMemorySize, SMEM_BYTES);
        attr_done = 1;
    }

    // round MMA operands to exact tf32 values
    rna_copy<<<(NROWS * DIM / 4 + 255) / 256, 256>>>(X, Xr, NROWS * DIM / 4);
    rna_copy<<<(DIM * DIM / 4 + 255) / 256, 256>>>(dw1, Wr + 0 * DIM * DIM, DIM * DIM / 4);
    rna_copy<<<(DIM * DIM / 4 + 255) / 256, 256>>>(dw2, Wr + 1 * DIM * DIM, DIM * DIM / 4);
    rna_copy<<<(DIM * DIM / 4 + 255) / 256, 256>>>(dw3, Wr + 2 * DIM * DIM, DIM * DIM / 4);

    dim3 gQKV(4, 256, 1);
    tc_gemm<0><<<gQKV, 256, SMEM_BYTES>>>(Xr, Wr + 0 * DIM * DIM, db1, Q);
    tc_gemm<0><<<gQKV, 256, SMEM_BYTES>>>(Xr, Wr + 1 * DIM * DIM, db2, K);
    tc_gemm<0><<<gQKV, 256, SMEM_BYTES>>>(Xr, Wr + 2 * DIM * DIM, db3, V);

    dim3 gS(4, 4, NBLK);
    tc_gemm<1><<<gS, 256, SMEM_BYTES>>>(Q, K, mask, S);

    softmax_rows<<<NBLK * BL, 128>>>();

    dim3 gO(4, 4, NBLK);
    tc_gemm<2><<<gO, 256, SMEM_BYTES>>>(S, V, X, out);

    ln_rows<<<NROWS, 128>>>(out);
}

// round 4
// speedup vs baseline: 5.4572x; 1.5356x over previous
#include <cuda_runtime.h>
#include <cuda_bf16.h>
#include <cstdint>
#include <math.h>

#define BL 512
#define DIM 512
#define NROWS 32768
#define NBLK 64

// Scratch (allocation-free rule: __device__ globals)
__device__ __nv_bfloat16 g_Xh [(size_t)NROWS*DIM];
__device__ __nv_bfloat16 g_Wth[(size_t)3*DIM*DIM];
__device__ __nv_bfloat16 g_Qh [(size_t)NROWS*DIM];
__device__ __nv_bfloat16 g_Kh [(size_t)NROWS*DIM];
__device__ __nv_bfloat16 g_Vh [(size_t)NROWS*DIM];
__device__ __nv_bfloat16 g_Vth[(size_t)NROWS*DIM];
__device__ __nv_bfloat16 g_Ph [(size_t)NBLK*BL*BL];
__device__ float         g_S  [(size_t)NBLK*BL*BL];

// ---------------------------------------------------------------------------
__device__ __forceinline__ uint32_t smem_u32(const void* p) {
    uint32_t a;
    asm("{ .reg .u64 t; cvta.to.shared.u64 t, %1; cvt.u32.u64 %0, t; }" : "=r"(a) : "l"(p));
    return a;
}
#define CP16(dst, src) \
    asm volatile("cp.async.cg.shared.global [%0], [%1], 16;" :: "r"(dst), "l"(src))
#define CPCOMMIT() asm volatile("cp.async.commit_group;" ::: "memory")
#define CPWAIT1()  asm volatile("cp.async.wait_group 1;" ::: "memory")
#define CPWAIT0()  asm volatile("cp.async.wait_group 0;" ::: "memory")

__device__ __forceinline__ void mma16(float* c, const uint32_t* a, const uint32_t* b) {
    asm volatile(
        "mma.sync.aligned.m16n8k16.row.col.f32.bf16.bf16.f32 "
        "{%0,%1,%2,%3},{%4,%5,%6,%7},{%8,%9},{%0,%1,%2,%3};"
        : "+f"(c[0]), "+f"(c[1]), "+f"(c[2]), "+f"(c[3])
        : "r"(a[0]), "r"(a[1]), "r"(a[2]), "r"(a[3]),
          "r"(b[0]), "r"(b[1]));
}

// ---------------------------------------------------------------------------
// bf16 NT GEMM via mma.sync: C[128,128] = A[128x512] @ B[128x512]^T (+epilogue)
// Both operands K-major bf16. CTA 128x128, 8 warps (32x64 each), BK=64,
// double-buffered cp.async. Padded smem stride 36 u32 -> conflict-free LDS.
// MODE 0: C(bf16) = A@B^T + bias(fp32 row vec)
// MODE 1: C(fp32) = scale*(A@B^T) + (1-mask)*(-1e10)
// MODE 2: C(fp32) = A@B^T + residual(fp32)
// ---------------------------------------------------------------------------
#define STRIDE_U32 36
#define STAGE_U32  (128*STRIDE_U32)   /* 4608 u32 = 18432 B */
#define SMEM_BYTES (4*STAGE_U32*4)    /* 73728 B */

template<int MODE>
__global__ void __launch_bounds__(256, 2)
tc_gemm(const __nv_bfloat16* __restrict__ Ag, const __nv_bfloat16* __restrict__ Bg,
        const float* __restrict__ aux, void* __restrict__ Cg) {
    extern __shared__ uint32_t smu[];
    const uint32_t sb = smem_u32(smu);
    const int tid  = threadIdx.x;
    const int lane = tid & 31, wid = tid >> 5;
    const int wm = wid & 3, wn = wid >> 2;
    const int q  = lane & 3, rg = lane >> 2;

    const size_t zoff = (size_t)blockIdx.z * (BL * DIM);
    const int bm = blockIdx.y * 128, bn = blockIdx.x * 128;
    const __nv_bfloat16* A = Ag + (MODE == 0 ? (size_t)0 : zoff) + (size_t)bm * DIM;
    const __nv_bfloat16* B = Bg + (MODE == 0 ? (size_t)0 : zoff) + (size_t)bn * DIM;

    float acc[2][8][4];
#pragma unroll
    for (int i = 0; i < 2; i++)
#pragma unroll
        for (int j = 0; j < 8; j++)
#pragma unroll
            for (int k = 0; k < 4; k++) acc[i][j][k] = 0.f;

    // ---- async load of K-chunk c (64 bf16) into stage s ----
    auto load = [&](int c, int s) {
        const uint32_t as = sb + (uint32_t)s * STAGE_U32 * 4;
        const uint32_t bs = sb + (uint32_t)(2 + s) * STAGE_U32 * 4;
#pragma unroll
        for (int t = 0; t < 4; t++) {
            int idx = tid + t * 256;
            int r = idx >> 3, c8 = idx & 7;                 // 8x16B per 128B row
            uint32_t doff = (uint32_t)(r * STRIDE_U32 + c8 * 4) * 4;
            const __nv_bfloat16* sa = A + (size_t)r * DIM + c * 64 + c8 * 8;
            const __nv_bfloat16* sbp = B + (size_t)r * DIM + c * 64 + c8 * 8;
            CP16(as + doff, sa);
            CP16(bs + doff, sbp);
        }
        CPCOMMIT();
    };

    auto compute = [&](int s) {
        const uint32_t* as = smu + (size_t)s * STAGE_U32;
        const uint32_t* bs = smu + (size_t)(2 + s) * STAGE_U32;
        const int ar0 = wm * 32 + rg;
        const int nb0 = wn * 64 + rg;
#pragma unroll
        for (int ks = 0; ks < 4; ks++) {
            const int kk = ks * 8;                          // u32 (bf16x2) units
            uint32_t af[2][4];
#pragma unroll
            for (int mt = 0; mt < 2; mt++) {
                const int r0 = ar0 + mt * 16;
                af[mt][0] = as[r0 * STRIDE_U32 + kk + q];
                af[mt][1] = as[(r0 + 8) * STRIDE_U32 + kk + q];
                af[mt][2] = as[r0 * STRIDE_U32 + kk + q + 4];
                af[mt][3] = as[(r0 + 8) * STRIDE_U32 + kk + q + 4];
            }
            uint32_t bf[8][2];
#pragma unroll
            for (int nt = 0; nt < 8; nt++) {
                const int n0 = nb0 + nt * 8;
                bf[nt][0] = bs[n0 * STRIDE_U32 + kk + q];
                bf[nt][1] = bs[n0 * STRIDE_U32 + kk + q + 4];
            }
#pragma unroll
            for (int mt = 0; mt < 2; mt++)
#pragma unroll
                for (int nt = 0; nt < 8; nt++)
                    mma16(acc[mt][nt], af[mt], bf[nt]);
        }
    };

    load(0, 0);
    for (int c = 0; c < 8; c++) {
        const int s = c & 1;
        if (c + 1 < 8) { load(c + 1, s ^ 1); CPWAIT1(); }
        else           { CPWAIT0(); }
        __syncthreads();
        compute(s);
        __syncthreads();
    }

    // ---- epilogue ----
    const float scale = 0.04419417382415922f;  // 1/sqrt(512)
#pragma unroll
    for (int mt = 0; mt < 2; mt++)
#pragma unroll
    for (int nt = 0; nt < 8; nt++) {
        const int rl0 = bm + wm * 32 + mt * 16 + rg;
        const int cl  = bn + wn * 64 + nt * 8 + 2 * q;
#pragma unroll
        for (int h = 0; h < 2; h++) {
            const int r = rl0 + h * 8;
            float v0 = acc[mt][nt][2 * h + 0];
            float v1 = acc[mt][nt][2 * h + 1];
            if (MODE == 0) {
                float2 bv = *(const float2*)(aux + cl);
                v0 += bv.x; v1 += bv.y;
                __nv_bfloat162 o = __float22bfloat162_rn(make_float2(v0, v1));
                *(__nv_bfloat162*)((__nv_bfloat16*)Cg + (size_t)r * DIM + cl) = o;
            } else if (MODE == 1) {
                const size_t base = ((size_t)blockIdx.z * BL + r) * DIM + cl;
                float2 mv = *(const float2*)(aux + base);
                v0 = v0 * scale + (1.f - mv.x) * (-1e10f);
                v1 = v1 * scale + (1.f - mv.y) * (-1e10f);
                *(float2*)((float*)Cg + base) = make_float2(v0, v1);
            } else {
                const size_t base = ((size_t)blockIdx.z * BL + r) * DIM + cl;
                float2 rv = *(const float2*)(aux + base);
                *(float2*)((float*)Cg + base) = make_float2(v0 + rv.x, v1 + rv.y);
            }
        }
    }
}

// ---------------------------------------------------------------------------
// fp32 -> bf16 elementwise (8 elems/thread)
// ---------------------------------------------------------------------------
__global__ __launch_bounds__(256)
void cvt_bf16(const float4* __restrict__ src, uint2* __restrict__ dst, int n8) {
    int i = blockIdx.x * 256 + threadIdx.x;
    if (i < n8) {
        float4 a = src[2 * i], b = src[2 * i + 1];
        uint2 o;
        o.x = ((uint32_t)__bfloat16_as_ushort(__float2bfloat16(a.y)) << 16)
            |  (uint32_t)__bfloat16_as_ushort(__float2bfloat16(a.x));
        o.y = ((uint32_t)__bfloat16_as_ushort(__float2bfloat16(a.w)) << 16)
            |  (uint32_t)__bfloat16_as_ushort(__float2bfloat16(a.z));
        uint2 o2;
        o2.x = ((uint32_t)__bfloat16_as_ushort(__float2bfloat16(b.y)) << 16)
             |  (uint32_t)__bfloat16_as_ushort(__float2bfloat16(b.x));
        o2.y = ((uint32_t)__bfloat16_as_ushort(__float2bfloat16(b.w)) << 16)
             |  (uint32_t)__bfloat16_as_ushort(__float2bfloat16(b.z));
        dst[2 * i] = o;
        dst[2 * i + 1] = o2;
    }
}

// ---------------------------------------------------------------------------
// Transpose + convert: W fp32 [512,512] -> Wt bf16 [n][k]
// ---------------------------------------------------------------------------
__global__ __launch_bounds__(256)
void wt_cvt(const float* __restrict__ src, __nv_bfloat16* __restrict__ dst) {
    __shared__ float t[32][33];
    int x = blockIdx.x * 32 + threadIdx.x;
    int y = blockIdx.y * 32 + threadIdx.y;
#pragma unroll
    for (int j = 0; j < 32; j += 8)
        t[threadIdx.y + j][threadIdx.x] = src[(size_t)(y + j) * DIM + x];
    __syncthreads();
    x = blockIdx.y * 32 + threadIdx.x;
    y = blockIdx.x * 32 + threadIdx.y;
#pragma unroll
    for (int j = 0; j < 32; j += 8)
        dst[(size_t)(y + j) * DIM + x] = __float2bfloat16(t[threadIdx.x][threadIdx.y + j]);
}

// ---------------------------------------------------------------------------
// bf16 512x512 transpose per z-slice: Vt[n][k] = V[k][n]
// ---------------------------------------------------------------------------
__global__ __launch_bounds__(256)
void vt_bf16(const __nv_bfloat16* __restrict__ src, __nv_bfloat16* __restrict__ dst) {
    __shared__ __nv_bfloat16 t[32][34];
    const size_t zo = (size_t)blockIdx.z * DIM * DIM;
    int x = blockIdx.x * 32 + threadIdx.x;
    int y = blockIdx.y * 32 + threadIdx.y;
#pragma unroll
    for (int j = 0; j < 32; j += 8)
        t[threadIdx.y + j][threadIdx.x] = src[zo + (size_t)(y + j) * DIM + x];
    __syncthreads();
    x = blockIdx.y * 32 + threadIdx.x;
    y = blockIdx.x * 32 + threadIdx.y;
#pragma unroll
    for (int j = 0; j < 32; j += 8)
        dst[zo + (size_t)(y + j) * DIM + x] = t[threadIdx.x][threadIdx.y + j];
}

// ---------------------------------------------------------------------------
// Row softmax over 512 fp32 elems of g_S; writes bf16 P (g_Ph)
// ---------------------------------------------------------------------------
__global__ __launch_bounds__(128)
void softmax_rows() {
    const size_t row = blockIdx.x;
    const float4* p = (const float4*)(g_S + row * BL);
    const int tid = threadIdx.x;
    float4 v = p[tid];
    float m = fmaxf(fmaxf(v.x, v.y), fmaxf(v.z, v.w));
#pragma unroll
    for (int o = 16; o; o >>= 1) m = fmaxf(m, __shfl_xor_sync(0xFFFFFFFFu, m, o));
    __shared__ float sm[4];
    if ((tid & 31) == 0) sm[tid >> 5] = m;
    __syncthreads();
    m = fmaxf(fmaxf(sm[0], sm[1]), fmaxf(sm[2], sm[3]));
    v.x = __expf(v.x - m); v.y = __expf(v.y - m);
    v.z = __expf(v.z - m); v.w = __expf(v.w - m);
    float s = v.x + v.y + v.z + v.w;
#pragma unroll
    for (int o = 16; o; o >>= 1) s += __shfl_xor_sync(0xFFFFFFFFu, s, o);
    __shared__ float ss[4];
    if ((tid & 31) == 0) ss[tid >> 5] = s;
    __syncthreads();
    s = ss[0] + ss[1] + ss[2] + ss[3];
    float r = 1.f / s;
    __nv_bfloat162 lo = __float22bfloat162_rn(make_float2(v.x * r, v.y * r));
    __nv_bfloat162 hi = __float22bfloat162_rn(make_float2(v.z * r, v.w * r));
    uint2 o;
    o.x = *(uint32_t*)&lo;
    o.y = *(uint32_t*)&hi;
    ((uint2*)(g_Ph + row * BL))[tid] = o;
}

// ---------------------------------------------------------------------------
// LayerNorm rows in-place on d_out (eps=1e-3)
// ---------------------------------------------------------------------------
__global__ __launch_bounds__(128)
void ln_rows(float* __restrict__ out) {
    const size_t row = blockIdx.x;
    float4* p = (float4*)(out + row * DIM);
    const int tid = threadIdx.x;
    float4 v = p[tid];
    float s  = v.x + v.y + v.z + v.w;
    float sq = v.x*v.x + v.y*v.y + v.z*v.z + v.w*v.w;
#pragma unroll
    for (int o = 16; o; o >>= 1) {
        s  += __shfl_xor_sync(0xFFFFFFFFu, s,  o);
        sq += __shfl_xor_sync(0xFFFFFFFFu, sq, o);
    }
    __shared__ float ws[4], wq[4];
    if ((tid & 31) == 0) { ws[tid >> 5] = s; wq[tid >> 5] = sq; }
    __syncthreads();
    s  = ws[0] + ws[1] + ws[2] + ws[3];
    sq = wq[0] + wq[1] + wq[2] + wq[3];
    const float inv = 1.f / (float)DIM;
    float mean = s * inv;
    float var  = sq * inv - mean * mean;
    float r = rsqrtf(var + 1e-3f);
    v.x = (v.x - mean) * r; v.y = (v.y - mean) * r;
    v.z = (v.z - mean) * r; v.w = (v.w - mean) * r;
    p[tid] = v;
}

// ---------------------------------------------------------------------------
extern "C" void kernel_launch(void* const* d_in, const int* in_sizes, int n_in,
                              void* d_out, int out_size) {
    const float* X    = (const float*)d_in[0];
    const float* mask = (const float*)d_in[1];
    const float* dw1  = (const float*)d_in[2];
    const float* dw2  = (const float*)d_in[3];
    const float* dw3  = (const float*)d_in[4];
    const float* db1  = (const float*)d_in[5];
    const float* db2  = (const float*)d_in[6];
    const float* db3  = (const float*)d_in[7];
    float* out = (float*)d_out;

    __nv_bfloat16 *Xh, *Wth, *Qh, *Kh, *Vh, *Vth, *Ph;
    float *S;
    cudaGetSymbolAddress((void**)&Xh,  g_Xh);
    cudaGetSymbolAddress((void**)&Wth, g_Wth);
    cudaGetSymbolAddress((void**)&Qh,  g_Qh);
    cudaGetSymbolAddress((void**)&Kh,  g_Kh);
    cudaGetSymbolAddress((void**)&Vh,  g_Vh);
    cudaGetSymbolAddress((void**)&Vth, g_Vth);
    cudaGetSymbolAddress((void**)&Ph,  g_Ph);
    cudaGetSymbolAddress((void**)&S,   g_S);

    static int attr_done = 0;
    if (!attr_done) {
        cudaFuncSetAttribute(tc_gemm<0>, cudaFuncAttributeMaxDynamicSharedMemorySize, SMEM_BYTES);
        cudaFuncSetAttribute(tc_gemm<1>, cudaFuncAttributeMaxDynamicSharedMemorySize, SMEM_BYTES);
        cudaFuncSetAttribute(tc_gemm<2>, cudaFuncAttributeMaxDynamicSharedMemorySize, SMEM_BYTES);
        attr_done = 1;
    }

    // Convert operands to bf16 (weights transposed to K-major)
    cvt_bf16<<<(NROWS * DIM / 8 + 255) / 256, 256>>>((const float4*)X, (uint2*)Xh, NROWS * DIM / 8);
    dim3 tblk(32, 8);
    wt_cvt<<<dim3(16, 16), tblk>>>(dw1, Wth + 0 * DIM * DIM);
    wt_cvt<<<dim3(16, 16), tblk>>>(dw2, Wth + 1 * DIM * DIM);
    wt_cvt<<<dim3(16, 16), tblk>>>(dw3, Wth + 2 * DIM * DIM);

    dim3 gQKV(4, 256, 1);
    tc_gemm<0><<<gQKV, 256, SMEM_BYTES>>>(Xh, Wth + 0 * DIM * DIM, db1, Qh);
    tc_gemm<0><<<gQKV, 256, SMEM_BYTES>>>(Xh, Wth + 1 * DIM * DIM, db2, Kh);
    tc_gemm<0><<<gQKV, 256, SMEM_BYTES>>>(Xh, Wth + 2 * DIM * DIM, db3, Vh);

    vt_bf16<<<dim3(16, 16, NBLK), tblk>>>(Vh, Vth);

    dim3 gS(4, 4, NBLK);
    tc_gemm<1><<<gS, 256, SMEM_BYTES>>>(Qh, Kh, mask, S);

    softmax_rows<<<NBLK * BL, 128>>>();

    dim3 gO(4, 4, NBLK);
    tc_gemm<2><<<gO, 256, SMEM_BYTES>>>(Ph, Vth, X, out);

    ln_rows<<<NROWS, 128>>>(out);
}

// round 5
// speedup vs baseline: 5.9821x; 1.0962x over previous
#include <cuda_runtime.h>
#include <cuda_bf16.h>
#include <cstdint>
#include <math.h>

#define BL 512
#define DIM 512
#define NROWS 32768
#define NBLK 64

// Scratch (allocation-free rule: __device__ globals)
__device__ __nv_bfloat16 g_Xh [(size_t)NROWS*DIM];
__device__ __nv_bfloat16 g_Wth[(size_t)3*DIM*DIM];
__device__ __nv_bfloat16 g_Qh [(size_t)NROWS*DIM];
__device__ __nv_bfloat16 g_Kh [(size_t)NROWS*DIM];
__device__ __nv_bfloat16 g_Vh [(size_t)NROWS*DIM];
__device__ __nv_bfloat16 g_Vth[(size_t)NROWS*DIM];
__device__ __nv_bfloat16 g_Ph [(size_t)NBLK*BL*BL];
__device__ float         g_S  [(size_t)NBLK*BL*BL];

// ---------------------------------------------------------------------------
__device__ __forceinline__ uint32_t smem_u32(const void* p) {
    uint32_t a;
    asm("{ .reg .u64 t; cvta.to.shared.u64 t, %1; cvt.u32.u64 %0, t; }" : "=r"(a) : "l"(p));
    return a;
}
#define CP16(dst, src) \
    asm volatile("cp.async.cg.shared.global [%0], [%1], 16;" :: "r"(dst), "l"(src))
#define CPCOMMIT() asm volatile("cp.async.commit_group;" ::: "memory")
#define CPWAIT1()  asm volatile("cp.async.wait_group 1;" ::: "memory")
#define CPWAIT0()  asm volatile("cp.async.wait_group 0;" ::: "memory")
#define LDSM4(R, addr) \
    asm volatile("ldmatrix.sync.aligned.m8n8.x4.shared.b16 {%0,%1,%2,%3}, [%4];" \
        : "=r"((R)[0]), "=r"((R)[1]), "=r"((R)[2]), "=r"((R)[3]) : "r"(addr))

__device__ __forceinline__ void mma16(float* c, const uint32_t* a, const uint32_t* b) {
    asm volatile(
        "mma.sync.aligned.m16n8k16.row.col.f32.bf16.bf16.f32 "
        "{%0,%1,%2,%3},{%4,%5,%6,%7},{%8,%9},{%0,%1,%2,%3};"
        : "+f"(c[0]), "+f"(c[1]), "+f"(c[2]), "+f"(c[3])
        : "r"(a[0]), "r"(a[1]), "r"(a[2]), "r"(a[3]),
          "r"(b[0]), "r"(b[1]));
}

// ---------------------------------------------------------------------------
// Shared bf16 NT GEMM mainloop: acc[128x128] = A[128x512] @ B[128x512]^T
// Both operands K-major bf16. 8 warps (warp tile 32x64), BK=64,
// double-buffered cp.async, ldmatrix fragment loads.
// smem rows padded to 144 B (36 u32): LDS and LDSM both conflict-free.
// ---------------------------------------------------------------------------
#define ROW_BYTES   144
#define STAGE_BYTES (128*ROW_BYTES)   /* 18432 */
#define SMEM_BYTES  (4*STAGE_BYTES)   /* 73728 */

__device__ __forceinline__ void bf16_gemm_128x128(
    const __nv_bfloat16* __restrict__ A, const __nv_bfloat16* __restrict__ B,
    uint32_t sb, int tid, float acc[2][8][4])
{
    const int lane = tid & 31, wid = tid >> 5;
    const int wm = wid & 3, wn = wid >> 2;

    // ldmatrix per-lane addressing (A: 16x16 tile as 4 8x8; B: 2 n-tiles)
    const int a_row = wm * 32 + (lane & 15);
    const int a_kb  = (lane >> 4) * 16;                       // bytes
    const int b_row = wn * 64 + ((lane >> 4) << 3) + (lane & 7);
    const int b_kb  = ((lane >> 3) & 1) * 16;

    const uint32_t a_base = sb + (uint32_t)(a_row * ROW_BYTES) + a_kb;
    const uint32_t b_base = sb + 2 * STAGE_BYTES + (uint32_t)(b_row * ROW_BYTES) + b_kb;

    // cp.async of K-chunk c (64 bf16 per row) into stage s
    auto load = [&](int c, int s) {
        const uint32_t as = sb + (uint32_t)s * STAGE_BYTES;
        const uint32_t bs = sb + (uint32_t)(2 + s) * STAGE_BYTES;
#pragma unroll
        for (int t = 0; t < 4; t++) {
            int idx = tid + t * 256;
            int r = idx >> 3, c8 = idx & 7;
            uint32_t doff = (uint32_t)(r * ROW_BYTES + c8 * 16);
            CP16(as + doff, A + (size_t)r * DIM + c * 64 + c8 * 8);
            CP16(bs + doff, B + (size_t)r * DIM + c * 64 + c8 * 8);
        }
        CPCOMMIT();
    };

    load(0, 0);
    for (int c = 0; c < 8; c++) {
        const int s = c & 1;
        if (c + 1 < 8) { load(c + 1, s ^ 1); CPWAIT1(); }
        else           { CPWAIT0(); }
        __syncthreads();
        const uint32_t aaddr = a_base + s * STAGE_BYTES;
        const uint32_t baddr = b_base + s * STAGE_BYTES;
#pragma unroll
        for (int ks = 0; ks < 4; ks++) {
            uint32_t af[2][4], bf[4][4];
            LDSM4(af[0], aaddr + ks * 32);
            LDSM4(af[1], aaddr + ks * 32 + 16 * ROW_BYTES);
#pragma unroll
            for (int g = 0; g < 4; g++)
                LDSM4(bf[g], baddr + ks * 32 + g * 16 * ROW_BYTES);
#pragma unroll
            for (int mt = 0; mt < 2; mt++)
#pragma unroll
                for (int g = 0; g < 4; g++) {
                    mma16(acc[mt][2 * g + 0], af[mt], &bf[g][0]);
                    mma16(acc[mt][2 * g + 1], af[mt], &bf[g][2]);
                }
        }
        __syncthreads();
    }
}

#define ACC_INIT(acc)                                         \
    float acc[2][8][4];                                       \
    _Pragma("unroll") for (int i = 0; i < 2; i++)             \
    _Pragma("unroll") for (int j = 0; j < 8; j++)             \
    _Pragma("unroll") for (int k = 0; k < 4; k++) acc[i][j][k] = 0.f;

// ---------------------------------------------------------------------------
// QKV: grid (4, 256, 3); z selects weight/bias/output. C bf16 = X@Wt^T + bias
// ---------------------------------------------------------------------------
__global__ void __launch_bounds__(256, 2)
tc_gemm_qkv(const __nv_bfloat16* __restrict__ Xh, const __nv_bfloat16* __restrict__ Wth,
            const float* __restrict__ b0, const float* __restrict__ b1,
            const float* __restrict__ b2,
            __nv_bfloat16* __restrict__ Qh, __nv_bfloat16* __restrict__ Kh,
            __nv_bfloat16* __restrict__ Vh)
{
    extern __shared__ uint32_t smu[];
    const uint32_t sb = smem_u32(smu);
    const int tid = threadIdx.x;
    const int z = blockIdx.z;
    const int bm = blockIdx.y * 128, bn = blockIdx.x * 128;

    const __nv_bfloat16* A = Xh + (size_t)bm * DIM;
    const __nv_bfloat16* B = Wth + (size_t)z * DIM * DIM + (size_t)bn * DIM;
    const float* bias = (z == 0) ? b0 : (z == 1) ? b1 : b2;
    __nv_bfloat16* C = (z == 0) ? Qh : (z == 1) ? Kh : Vh;

    ACC_INIT(acc);
    bf16_gemm_128x128(A, B, sb, tid, acc);

    const int lane = tid & 31, wid = tid >> 5;
    const int wm = wid & 3, wn = wid >> 2;
    const int q = lane & 3, rg = lane >> 2;
#pragma unroll
    for (int mt = 0; mt < 2; mt++)
#pragma unroll
    for (int nt = 0; nt < 8; nt++) {
        const int rl0 = bm + wm * 32 + mt * 16 + rg;
        const int cl  = bn + wn * 64 + nt * 8 + 2 * q;
        float2 bv = *(const float2*)(bias + cl);
#pragma unroll
        for (int h = 0; h < 2; h++) {
            const int r = rl0 + h * 8;
            float v0 = acc[mt][nt][2 * h + 0] + bv.x;
            float v1 = acc[mt][nt][2 * h + 1] + bv.y;
            __nv_bfloat162 o = __float22bfloat162_rn(make_float2(v0, v1));
            *(__nv_bfloat162*)(C + (size_t)r * DIM + cl) = o;
        }
    }
}

// ---------------------------------------------------------------------------
// MODE 1: S fp32 = scale*(Q@K^T) + (1-mask)*(-1e10)   grid (4, 4, 64)
// MODE 2: out fp32 = P@Vt^T + X                       grid (4, 4, 64)
// ---------------------------------------------------------------------------
template<int MODE>
__global__ void __launch_bounds__(256, 2)
tc_gemm(const __nv_bfloat16* __restrict__ Ag, const __nv_bfloat16* __restrict__ Bg,
        const float* __restrict__ aux, float* __restrict__ Cg)
{
    extern __shared__ uint32_t smu[];
    const uint32_t sb = smem_u32(smu);
    const int tid = threadIdx.x;
    const size_t zoff = (size_t)blockIdx.z * (BL * DIM);
    const int bm = blockIdx.y * 128, bn = blockIdx.x * 128;
    const __nv_bfloat16* A = Ag + zoff + (size_t)bm * DIM;
    const __nv_bfloat16* B = Bg + zoff + (size_t)bn * DIM;

    ACC_INIT(acc);
    bf16_gemm_128x128(A, B, sb, tid, acc);

    const int lane = tid & 31, wid = tid >> 5;
    const int wm = wid & 3, wn = wid >> 2;
    const int q = lane & 3, rg = lane >> 2;
    const float scale = 0.04419417382415922f;  // 1/sqrt(512)
#pragma unroll
    for (int mt = 0; mt < 2; mt++)
#pragma unroll
    for (int nt = 0; nt < 8; nt++) {
        const int rl0 = bm + wm * 32 + mt * 16 + rg;
        const int cl  = bn + wn * 64 + nt * 8 + 2 * q;
#pragma unroll
        for (int h = 0; h < 2; h++) {
            const int r = rl0 + h * 8;
            const size_t base = ((size_t)blockIdx.z * BL + r) * DIM + cl;
            float v0 = acc[mt][nt][2 * h + 0];
            float v1 = acc[mt][nt][2 * h + 1];
            float2 xv = *(const float2*)(aux + base);
            if (MODE == 1) {
                v0 = v0 * scale + (1.f - xv.x) * (-1e10f);
                v1 = v1 * scale + (1.f - xv.y) * (-1e10f);
            } else {
                v0 += xv.x; v1 += xv.y;
            }
            *(float2*)(Cg + base) = make_float2(v0, v1);
        }
    }
}

// ---------------------------------------------------------------------------
// fp32 -> bf16 elementwise (8 elems/thread)
// ---------------------------------------------------------------------------
__global__ __launch_bounds__(256)
void cvt_bf16(const float4* __restrict__ src, uint2* __restrict__ dst, int n8) {
    int i = blockIdx.x * 256 + threadIdx.x;
    if (i < n8) {
        float4 a = src[2 * i], b = src[2 * i + 1];
        uint2 o, o2;
        o.x = ((uint32_t)__bfloat16_as_ushort(__float2bfloat16(a.y)) << 16)
            |  (uint32_t)__bfloat16_as_ushort(__float2bfloat16(a.x));
        o.y = ((uint32_t)__bfloat16_as_ushort(__float2bfloat16(a.w)) << 16)
            |  (uint32_t)__bfloat16_as_ushort(__float2bfloat16(a.z));
        o2.x = ((uint32_t)__bfloat16_as_ushort(__float2bfloat16(b.y)) << 16)
             |  (uint32_t)__bfloat16_as_ushort(__float2bfloat16(b.x));
        o2.y = ((uint32_t)__bfloat16_as_ushort(__float2bfloat16(b.w)) << 16)
             |  (uint32_t)__bfloat16_as_ushort(__float2bfloat16(b.z));
        dst[2 * i] = o;
        dst[2 * i + 1] = o2;
    }
}

// ---------------------------------------------------------------------------
// Transpose + convert: W fp32 [512,512] -> Wt bf16 [n][k]; grid.z selects W
// ---------------------------------------------------------------------------
__global__ __launch_bounds__(256)
void wt_cvt(const float* __restrict__ w0, const float* __restrict__ w1,
            const float* __restrict__ w2, __nv_bfloat16* __restrict__ dst) {
    __shared__ float t[32][33];
    const int z = blockIdx.z;
    const float* src = (z == 0) ? w0 : (z == 1) ? w1 : w2;
    __nv_bfloat16* d = dst + (size_t)z * DIM * DIM;
    int x = blockIdx.x * 32 + threadIdx.x;
    int y = blockIdx.y * 32 + threadIdx.y;
#pragma unroll
    for (int j = 0; j < 32; j += 8)
        t[threadIdx.y + j][threadIdx.x] = src[(size_t)(y + j) * DIM + x];
    __syncthreads();
    x = blockIdx.y * 32 + threadIdx.x;
    y = blockIdx.x * 32 + threadIdx.y;
#pragma unroll
    for (int j = 0; j < 32; j += 8)
        d[(size_t)(y + j) * DIM + x] = __float2bfloat16(t[threadIdx.x][threadIdx.y + j]);
}

// ---------------------------------------------------------------------------
// bf16 512x512 transpose per z-slice: Vt[n][k] = V[k][n]
// ---------------------------------------------------------------------------
__global__ __launch_bounds__(256)
void vt_bf16(const __nv_bfloat16* __restrict__ src, __nv_bfloat16* __restrict__ dst) {
    __shared__ __nv_bfloat16 t[32][34];
    const size_t zo = (size_t)blockIdx.z * DIM * DIM;
    int x = blockIdx.x * 32 + threadIdx.x;
    int y = blockIdx.y * 32 + threadIdx.y;
#pragma unroll
    for (int j = 0; j < 32; j += 8)
        t[threadIdx.y + j][threadIdx.x] = src[zo + (size_t)(y + j) * DIM + x];
    __syncthreads();
    x = blockIdx.y * 32 + threadIdx.x;
    y = blockIdx.x * 32 + threadIdx.y;
#pragma unroll
    for (int j = 0; j < 32; j += 8)
        dst[zo + (size_t)(y + j) * DIM + x] = t[threadIdx.x][threadIdx.y + j];
}

// ---------------------------------------------------------------------------
// Row softmax over 512 fp32 elems of g_S; writes bf16 P (g_Ph)
// ---------------------------------------------------------------------------
__global__ __launch_bounds__(128)
void softmax_rows() {
    const size_t row = blockIdx.x;
    const float4* p = (const float4*)(g_S + row * BL);
    const int tid = threadIdx.x;
    float4 v = p[tid];
    float m = fmaxf(fmaxf(v.x, v.y), fmaxf(v.z, v.w));
#pragma unroll
    for (int o = 16; o; o >>= 1) m = fmaxf(m, __shfl_xor_sync(0xFFFFFFFFu, m, o));
    __shared__ float sm[4];
    if ((tid & 31) == 0) sm[tid >> 5] = m;
    __syncthreads();
    m = fmaxf(fmaxf(sm[0], sm[1]), fmaxf(sm[2], sm[3]));
    v.x = __expf(v.x - m); v.y = __expf(v.y - m);
    v.z = __expf(v.z - m); v.w = __expf(v.w - m);
    float s = v.x + v.y + v.z + v.w;
#pragma unroll
    for (int o = 16; o; o >>= 1) s += __shfl_xor_sync(0xFFFFFFFFu, s, o);
    __shared__ float ss[4];
    if ((tid & 31) == 0) ss[tid >> 5] = s;
    __syncthreads();
    s = ss[0] + ss[1] + ss[2] + ss[3];
    float r = 1.f / s;
    __nv_bfloat162 lo = __float22bfloat162_rn(make_float2(v.x * r, v.y * r));
    __nv_bfloat162 hi = __float22bfloat162_rn(make_float2(v.z * r, v.w * r));
    uint2 o;
    o.x = *(uint32_t*)&lo;
    o.y = *(uint32_t*)&hi;
    ((uint2*)(g_Ph + row * BL))[tid] = o;
}

// ---------------------------------------------------------------------------
// LayerNorm rows in-place on d_out (eps=1e-3)
// ---------------------------------------------------------------------------
__global__ __launch_bounds__(128)
void ln_rows(float* __restrict__ out) {
    const size_t row = blockIdx.x;
    float4* p = (float4*)(out + row * DIM);
    const int tid = threadIdx.x;
    float4 v = p[tid];
    float s  = v.x + v.y + v.z + v.w;
    float sq = v.x*v.x + v.y*v.y + v.z*v.z + v.w*v.w;
#pragma unroll
    for (int o = 16; o; o >>= 1) {
        s  += __shfl_xor_sync(0xFFFFFFFFu, s,  o);
        sq += __shfl_xor_sync(0xFFFFFFFFu, sq, o);
    }
    __shared__ float ws[4], wq[4];
    if ((tid & 31) == 0) { ws[tid >> 5] = s; wq[tid >> 5] = sq; }
    __syncthreads();
    s  = ws[0] + ws[1] + ws[2] + ws[3];
    sq = wq[0] + wq[1] + wq[2] + wq[3];
    const float inv = 1.f / (float)DIM;
    float mean = s * inv;
    float var  = sq * inv - mean * mean;
    float r = rsqrtf(var + 1e-3f);
    v.x = (v.x - mean) * r; v.y = (v.y - mean) * r;
    v.z = (v.z - mean) * r; v.w = (v.w - mean) * r;
    p[tid] = v;
}

// ---------------------------------------------------------------------------
extern "C" void kernel_launch(void* const* d_in, const int* in_sizes, int n_in,
                              void* d_out, int out_size) {
    const float* X    = (const float*)d_in[0];
    const float* mask = (const float*)d_in[1];
    const float* dw1  = (const float*)d_in[2];
    const float* dw2  = (const float*)d_in[3];
    const float* dw3  = (const float*)d_in[4];
    const float* db1  = (const float*)d_in[5];
    const float* db2  = (const float*)d_in[6];
    const float* db3  = (const float*)d_in[7];
    float* out = (float*)d_out;

    __nv_bfloat16 *Xh, *Wth, *Qh, *Kh, *Vh, *Vth, *Ph;
    float *S;
    cudaGetSymbolAddress((void**)&Xh,  g_Xh);
    cudaGetSymbolAddress((void**)&Wth, g_Wth);
    cudaGetSymbolAddress((void**)&Qh,  g_Qh);
    cudaGetSymbolAddress((void**)&Kh,  g_Kh);
    cudaGetSymbolAddress((void**)&Vh,  g_Vh);
    cudaGetSymbolAddress((void**)&Vth, g_Vth);
    cudaGetSymbolAddress((void**)&Ph,  g_Ph);
    cudaGetSymbolAddress((void**)&S,   g_S);

    static int attr_done = 0;
    if (!attr_done) {
        cudaFuncSetAttribute(tc_gemm_qkv, cudaFuncAttributeMaxDynamicSharedMemorySize, SMEM_BYTES);
        cudaFuncSetAttribute(tc_gemm<1>, cudaFuncAttributeMaxDynamicSharedMemorySize, SMEM_BYTES);
        cudaFuncSetAttribute(tc_gemm<2>, cudaFuncAttributeMaxDynamicSharedMemorySize, SMEM_BYTES);
        attr_done = 1;
    }

    // Convert operands to bf16 (weights transposed to K-major)
    cvt_bf16<<<(NROWS * DIM / 8 + 255) / 256, 256>>>((const float4*)X, (uint2*)Xh, NROWS * DIM / 8);
    dim3 tblk(32, 8);
    wt_cvt<<<dim3(16, 16, 3), tblk>>>(dw1, dw2, dw3, Wth);

    tc_gemm_qkv<<<dim3(4, 256, 3), 256, SMEM_BYTES>>>(Xh, Wth, db1, db2, db3, Qh, Kh, Vh);

    vt_bf16<<<dim3(16, 16, NBLK), tblk>>>(Vh, Vth);

    tc_gemm<1><<<dim3(4, 4, NBLK), 256, SMEM_BYTES>>>(Qh, Kh, mask, S);

    softmax_rows<<<NBLK * BL, 128>>>();

    tc_gemm<2><<<dim3(4, 4, NBLK), 256, SMEM_BYTES>>>(Ph, Vth, X, out);

    ln_rows<<<NROWS, 128>>>(out);
}